// round 1
// baseline (speedup 1.0000x reference)
#include <cuda_runtime.h>
#include <math.h>

#define B_   2
#define T_   1024
#define D_   6144
#define NQ_  48
#define NKV_ 8
#define HD_  128
#define GQ_  (NQ_ / NKV_)          // 6 query heads per kv head
#define MULT_     0.08838834764831845f
#define MAX_ATTN_ 30.0f

// ---------------- scratch (allocation-free: __device__ globals) ----------------
__device__ float g_q[(size_t)B_ * T_ * NQ_ * HD_];    // 50.3 MB
__device__ float g_k[(size_t)B_ * T_ * NKV_ * HD_];   //  8.4 MB
__device__ float g_v[(size_t)B_ * T_ * NKV_ * HD_];   //  8.4 MB
__device__ float g_attn[(size_t)B_ * T_ * NQ_ * HD_]; // 50.3 MB

// ---------------- fp32 tiled GEMM: Y[M,N] = X[M,K] @ W[K,N] (+ bias) ----------
// BM=BN=128, BK=16, 256 threads, 8x8 microtile per thread.
__global__ __launch_bounds__(256) void gemm_bias_kernel(
    const float* __restrict__ X, const float* __restrict__ W,
    const float* __restrict__ bias, float* __restrict__ Y,
    int M, int N, int K)
{
    __shared__ float As[16][128];   // stored k-major (transposed)
    __shared__ float Bs[16][128];

    const int tid = threadIdx.x;
    const int tx = tid & 15;        // 0..15 -> col group
    const int ty = tid >> 4;        // 0..15 -> row group
    const int m0 = blockIdx.y * 128;
    const int n0 = blockIdx.x * 128;

    float acc[8][8];
    #pragma unroll
    for (int i = 0; i < 8; i++)
        #pragma unroll
        for (int j = 0; j < 8; j++) acc[i][j] = 0.f;

    for (int k0 = 0; k0 < K; k0 += 16) {
        // load A tile 128x16 (transposed into As[k][m])
        {
            const int r = tid >> 2;            // 0..63
            const int c = (tid & 3) * 4;       // 0,4,8,12
            #pragma unroll
            for (int rr = 0; rr < 2; rr++) {
                const int row = r + rr * 64;
                float4 v = *(const float4*)&X[(size_t)(m0 + row) * K + k0 + c];
                As[c + 0][row] = v.x;
                As[c + 1][row] = v.y;
                As[c + 2][row] = v.z;
                As[c + 3][row] = v.w;
            }
        }
        // load B tile 16x128
        {
            const int r = tid >> 5;            // 0..7
            const int c = (tid & 31) * 4;      // 0..124
            #pragma unroll
            for (int rr = 0; rr < 2; rr++) {
                const int row = r + rr * 8;
                *(float4*)&Bs[row][c] =
                    *(const float4*)&W[(size_t)(k0 + row) * N + n0 + c];
            }
        }
        __syncthreads();

        #pragma unroll
        for (int k = 0; k < 16; k++) {
            float a[8], b[8];
            *(float4*)&a[0] = *(float4*)&As[k][ty * 8];
            *(float4*)&a[4] = *(float4*)&As[k][ty * 8 + 4];
            *(float4*)&b[0] = *(float4*)&Bs[k][tx * 8];
            *(float4*)&b[4] = *(float4*)&Bs[k][tx * 8 + 4];
            #pragma unroll
            for (int i = 0; i < 8; i++)
                #pragma unroll
                for (int j = 0; j < 8; j++)
                    acc[i][j] = fmaf(a[i], b[j], acc[i][j]);
        }
        __syncthreads();
    }

    #pragma unroll
    for (int i = 0; i < 8; i++) {
        const int row = m0 + ty * 8 + i;
        #pragma unroll
        for (int j = 0; j < 8; j += 4) {
            const int col = n0 + tx * 8 + j;
            float4 v;
            float b0 = bias ? bias[col + 0] : 0.f;
            float b1 = bias ? bias[col + 1] : 0.f;
            float b2 = bias ? bias[col + 2] : 0.f;
            float b3 = bias ? bias[col + 3] : 0.f;
            v.x = acc[i][j + 0] + b0;
            v.y = acc[i][j + 1] + b1;
            v.z = acc[i][j + 2] + b2;
            v.w = acc[i][j + 3] + b3;
            *(float4*)&Y[(size_t)row * N + col] = v;
        }
    }
}

// ---------------- RoPE (NeoX half-rotation), in place ----------------
// x layout: (b, t, H, 128); thread handles pair (j, j+64), j<64.
__global__ __launch_bounds__(256) void rope_kernel(float* __restrict__ x, int H, int total)
{
    const int idx = blockIdx.x * blockDim.x + threadIdx.x;
    if (idx >= total) return;
    const int j   = idx & 63;
    const int lin = idx >> 6;               // (b*T + t)*H + h
    const int t   = (lin / H) % T_;

    const double invf  = exp(-log(10000.0) * (double)j / 64.0);
    double ph = (double)t * invf;
    const double twopi = 6.283185307179586476925286766559;
    ph -= twopi * floor(ph / twopi);
    float s, c;
    sincosf((float)ph, &s, &c);

    const size_t base = (size_t)lin * HD_;
    const float x1 = x[base + j];
    const float x2 = x[base + j + 64];
    x[base + j]      = x1 * c - x2 * s;
    x[base + j + 64] = x2 * c + x1 * s;
}

// ---------------- causal GQA flash attention with tanh soft-cap ----------------
// Grid: (T/64, B*NQ). Block: 256 threads.
// SMEM: Qs[64][132], Kst[128][68] (d-major), Vs[64][132], Es[64][68], den[64]
#define QS_PITCH 132
#define KT_PITCH 68
#define ES_PITCH 68

__global__ __launch_bounds__(256) void attn_kernel(
    const float* __restrict__ gq, const float* __restrict__ gk,
    const float* __restrict__ gv, float* __restrict__ gout)
{
    extern __shared__ float sm[];
    float* Qs  = sm;                           // 64*132
    float* Kst = Qs + 64 * QS_PITCH;           // 128*68  (Kst[d][j])
    float* Vs  = Kst + 128 * KT_PITCH;         // 64*132
    float* Es  = Vs + 64 * QS_PITCH;           // 64*68
    float* den = Es + 64 * ES_PITCH;           // 64

    const int bh  = blockIdx.y;
    const int b   = bh / NQ_;
    const int h   = bh % NQ_;
    const int kvh = h / GQ_;
    const int q0  = blockIdx.x * 64;

    const int tid = threadIdx.x;
    const int tx  = tid & 15;
    const int ty  = tid >> 4;

    // load Q tile (64 rows x 128)
    for (int i = tid; i < 64 * 32; i += 256) {
        const int row = i >> 5;
        const int c   = (i & 31) * 4;
        float4 v = *(const float4*)&gq[((((size_t)b * T_ + q0 + row) * NQ_) + h) * HD_ + c];
        *(float4*)&Qs[row * QS_PITCH + c] = v;
    }
    if (tid < 64) den[tid] = 0.f;

    float acc[4][8];
    #pragma unroll
    for (int r = 0; r < 4; r++)
        #pragma unroll
        for (int j = 0; j < 8; j++) acc[r][j] = 0.f;

    const int nkb = blockIdx.x + 1;   // causal: key blocks 0..blockIdx.x
    for (int kb = 0; kb < nkb; kb++) {
        __syncthreads();   // previous iter's consumers done before overwrite
        // load K (transposed to d-major) and V tiles
        for (int i = tid; i < 64 * 32; i += 256) {
            const int row = i >> 5;
            const int c   = (i & 31) * 4;
            const size_t base = ((((size_t)b * T_ + kb * 64 + row) * NKV_) + kvh) * HD_ + c;
            float4 kvec = *(const float4*)&gk[base];
            Kst[(c + 0) * KT_PITCH + row] = kvec.x;
            Kst[(c + 1) * KT_PITCH + row] = kvec.y;
            Kst[(c + 2) * KT_PITCH + row] = kvec.z;
            Kst[(c + 3) * KT_PITCH + row] = kvec.w;
            *(float4*)&Vs[row * QS_PITCH + c] = *(const float4*)&gv[base];
        }
        __syncthreads();

        // S = Q K^T   (4x4 per thread)
        float s[4][4];
        #pragma unroll
        for (int r = 0; r < 4; r++)
            #pragma unroll
            for (int c = 0; c < 4; c++) s[r][c] = 0.f;

        #pragma unroll 4
        for (int d = 0; d < HD_; d++) {
            float qv[4];
            #pragma unroll
            for (int r = 0; r < 4; r++) qv[r] = Qs[(ty * 4 + r) * QS_PITCH + d];
            float4 kv = *(float4*)&Kst[d * KT_PITCH + tx * 4];
            const float kvv[4] = {kv.x, kv.y, kv.z, kv.w};
            #pragma unroll
            for (int r = 0; r < 4; r++)
                #pragma unroll
                for (int c = 0; c < 4; c++)
                    s[r][c] = fmaf(qv[r], kvv[c], s[r][c]);
        }

        // soft-cap + causal mask + exp -> Es
        #pragma unroll
        for (int r = 0; r < 4; r++) {
            const int qpos = q0 + ty * 4 + r;
            float4 ev;
            float e[4];
            #pragma unroll
            for (int c = 0; c < 4; c++) {
                const int kpos = kb * 64 + tx * 4 + c;
                float val = s[r][c] * MULT_;
                val = MAX_ATTN_ * tanhf(val * (1.0f / MAX_ATTN_));
                e[c] = (kpos <= qpos) ? expf(val) : 0.f;
            }
            ev.x = e[0]; ev.y = e[1]; ev.z = e[2]; ev.w = e[3];
            *(float4*)&Es[(ty * 4 + r) * ES_PITCH + tx * 4] = ev;
        }
        __syncthreads();

        // row denominators
        if (tid < 64) {
            float sum = 0.f;
            #pragma unroll 8
            for (int j = 0; j < 64; j++) sum += Es[tid * ES_PITCH + j];
            den[tid] += sum;
        }

        // O += E @ V   (4 rows x 8 cols per thread)
        #pragma unroll 4
        for (int k = 0; k < 64; k++) {
            float e[4];
            #pragma unroll
            for (int r = 0; r < 4; r++) e[r] = Es[(ty * 4 + r) * ES_PITCH + k];
            float4 va = *(float4*)&Vs[k * QS_PITCH + tx * 8];
            float4 vb = *(float4*)&Vs[k * QS_PITCH + tx * 8 + 4];
            const float vv[8] = {va.x, va.y, va.z, va.w, vb.x, vb.y, vb.z, vb.w};
            #pragma unroll
            for (int r = 0; r < 4; r++)
                #pragma unroll
                for (int j = 0; j < 8; j++)
                    acc[r][j] = fmaf(e[r], vv[j], acc[r][j]);
        }
    }
    __syncthreads();

    // normalize + write
    #pragma unroll
    for (int r = 0; r < 4; r++) {
        const int row = q0 + ty * 4 + r;
        const float inv = 1.f / den[ty * 4 + r];
        float4 oa, ob;
        oa.x = acc[r][0] * inv; oa.y = acc[r][1] * inv;
        oa.z = acc[r][2] * inv; oa.w = acc[r][3] * inv;
        ob.x = acc[r][4] * inv; ob.y = acc[r][5] * inv;
        ob.z = acc[r][6] * inv; ob.w = acc[r][7] * inv;
        float* dst = &gout[((((size_t)b * T_ + row) * NQ_) + h) * HD_ + tx * 8];
        *(float4*)&dst[0] = oa;
        *(float4*)&dst[4] = ob;
    }
}

// ---------------- launch ----------------
extern "C" void kernel_launch(void* const* d_in, const int* in_sizes, int n_in,
                              void* d_out, int out_size)
{
    const float* query = (const float*)d_in[0];
    const float* key   = (const float*)d_in[1];
    const float* value = (const float*)d_in[2];
    // d_in[3] = mask: exact causal tril — implemented analytically, unused.
    const float* wq = (const float*)d_in[4];
    const float* bq = (const float*)d_in[5];
    const float* wk = (const float*)d_in[6];
    const float* bk = (const float*)d_in[7];
    const float* wv = (const float*)d_in[8];
    const float* bv = (const float*)d_in[9];
    const float* wo = (const float*)d_in[10];
    float* out = (float*)d_out;

    float *qp, *kp, *vp, *ap;
    cudaGetSymbolAddress((void**)&qp, g_q);
    cudaGetSymbolAddress((void**)&kp, g_k);
    cudaGetSymbolAddress((void**)&vp, g_v);
    cudaGetSymbolAddress((void**)&ap, g_attn);

    const int M = B_ * T_;
    dim3 blk(256);

    gemm_bias_kernel<<<dim3((NQ_ * HD_) / 128, M / 128), blk>>>(query, wq, bq, qp, M, NQ_ * HD_, D_);
    gemm_bias_kernel<<<dim3((NKV_ * HD_) / 128, M / 128), blk>>>(key,   wk, bk, kp, M, NKV_ * HD_, D_);
    gemm_bias_kernel<<<dim3((NKV_ * HD_) / 128, M / 128), blk>>>(value, wv, bv, vp, M, NKV_ * HD_, D_);

    const int nq_pairs = B_ * T_ * NQ_ * 64;
    const int nk_pairs = B_ * T_ * NKV_ * 64;
    rope_kernel<<<(nq_pairs + 255) / 256, 256>>>(qp, NQ_, nq_pairs);
    rope_kernel<<<(nk_pairs + 255) / 256, 256>>>(kp, NKV_, nk_pairs);

    const size_t smem = (size_t)(64 * QS_PITCH + 128 * KT_PITCH + 64 * QS_PITCH
                                 + 64 * ES_PITCH + 64) * sizeof(float);
    cudaFuncSetAttribute(attn_kernel, cudaFuncAttributeMaxDynamicSharedMemorySize, (int)smem);
    attn_kernel<<<dim3(T_ / 64, B_ * NQ_), blk, smem>>>(qp, kp, vp, ap);

    gemm_bias_kernel<<<dim3(D_ / 128, M / 128), blk>>>(ap, wo, nullptr, out, M, D_, D_);
}

// round 3
// speedup vs baseline: 2.0472x; 2.0472x over previous
#include <cuda_runtime.h>
#include <cuda_bf16.h>
#include <cstdint>
#include <math.h>

#define B_   2
#define T_   1024
#define D_   6144
#define NQ_  48
#define NKV_ 8
#define HD_  128
#define GQ_  (NQ_ / NKV_)
#define MULT_     0.08838834764831845f
#define MAX_ATTN_ 30.0f
#define M_ROWS (B_ * T_)           // 2048

// ---------------- scratch (__device__ globals; no allocation) ----------------
__device__ float g_q[(size_t)B_ * T_ * NQ_ * HD_];
__device__ float g_k[(size_t)B_ * T_ * NKV_ * HD_];
__device__ float g_v[(size_t)B_ * T_ * NKV_ * HD_];
__device__ float g_attn[(size_t)B_ * T_ * NQ_ * HD_];
__device__ float2 g_rope[T_ * 64];

// bf16 split planes
__device__ __nv_bfloat16 g_xq_hi[(size_t)M_ROWS * D_];
__device__ __nv_bfloat16 g_xq_lo[(size_t)M_ROWS * D_];
__device__ __nv_bfloat16 g_xk_hi[(size_t)M_ROWS * D_];
__device__ __nv_bfloat16 g_xk_lo[(size_t)M_ROWS * D_];
__device__ __nv_bfloat16 g_xv_hi[(size_t)M_ROWS * D_];
__device__ __nv_bfloat16 g_xv_lo[(size_t)M_ROWS * D_];
__device__ __nv_bfloat16 g_wt_hi[(size_t)D_ * D_];   // [N,K] transposed weight, reused
__device__ __nv_bfloat16 g_wt_lo[(size_t)D_ * D_];

// ---------------- rope table + apply ----------------
__global__ void rope_table_kernel() {
    const int i = blockIdx.x * blockDim.x + threadIdx.x;   // < T_*64
    const int t = i >> 6, j = i & 63;
    const double invf = exp(-log(10000.0) * (double)j / 64.0);
    double ph = (double)t * invf;
    const double twopi = 6.283185307179586476925286766559;
    ph -= twopi * floor(ph / twopi);
    float s, c;
    sincosf((float)ph, &s, &c);
    g_rope[i] = make_float2(c, s);
}
__global__ __launch_bounds__(256) void rope_apply_kernel(float* __restrict__ x, int H, int total) {
    const int idx = blockIdx.x * blockDim.x + threadIdx.x;
    if (idx >= total) return;
    const int j = idx & 63;
    const int lin = idx >> 6;
    const int t = (lin / H) % T_;
    const float2 cs = g_rope[t * 64 + j];
    const size_t base = (size_t)lin * HD_;
    const float x1 = x[base + j];
    const float x2 = x[base + j + 64];
    x[base + j]      = x1 * cs.x - x2 * cs.y;
    x[base + j + 64] = x2 * cs.x + x1 * cs.y;
}

// ---------------- fp32 -> (hi, lo) bf16 split ----------------
__global__ __launch_bounds__(256) void conv_split_kernel(
    const float* __restrict__ x, __nv_bfloat16* __restrict__ hi,
    __nv_bfloat16* __restrict__ lo, int n4)
{
    const int i = blockIdx.x * blockDim.x + threadIdx.x;
    if (i >= n4) return;
    const float4 v = ((const float4*)x)[i];
    __nv_bfloat16 h0 = __float2bfloat16_rn(v.x);
    __nv_bfloat16 h1 = __float2bfloat16_rn(v.y);
    __nv_bfloat16 h2 = __float2bfloat16_rn(v.z);
    __nv_bfloat16 h3 = __float2bfloat16_rn(v.w);
    __nv_bfloat162* H = (__nv_bfloat162*)hi;
    __nv_bfloat162* L = (__nv_bfloat162*)lo;
    H[2 * i]     = __nv_bfloat162(h0, h1);
    H[2 * i + 1] = __nv_bfloat162(h2, h3);
    L[2 * i]     = __nv_bfloat162(__float2bfloat16_rn(v.x - __bfloat162float(h0)),
                                  __float2bfloat16_rn(v.y - __bfloat162float(h1)));
    L[2 * i + 1] = __nv_bfloat162(__float2bfloat16_rn(v.z - __bfloat162float(h2)),
                                  __float2bfloat16_rn(v.w - __bfloat162float(h3)));
}

// ---------------- W[K,N] fp32 -> Wt[N,K] (hi, lo) bf16 ----------------
__global__ void transpose_split_kernel(
    const float* __restrict__ W, __nv_bfloat16* __restrict__ Thi,
    __nv_bfloat16* __restrict__ Tlo, int K, int N)
{
    __shared__ float s[32][33];
    const int k0 = blockIdx.y * 32, n0 = blockIdx.x * 32;
    const int tx = threadIdx.x, ty = threadIdx.y;  // 32 x 8
    #pragma unroll
    for (int i = 0; i < 4; i++)
        s[ty + 8 * i][tx] = W[(size_t)(k0 + ty + 8 * i) * N + n0 + tx];
    __syncthreads();
    #pragma unroll
    for (int i = 0; i < 4; i++) {
        const float v = s[tx][ty + 8 * i];
        const __nv_bfloat16 h = __float2bfloat16_rn(v);
        const size_t o = (size_t)(n0 + ty + 8 * i) * K + k0 + tx;
        Thi[o] = h;
        Tlo[o] = __float2bfloat16_rn(v - __bfloat162float(h));
    }
}

// ---------------- split-bf16 HMMA GEMM: Y[M,N] = X[M,K] @ Wt[N,K]^T ---------
// BM=128, BN=128, BK=32. 256 threads = 8 warps (2x4), warp tile 64x32.
// SMEM: 2 stages x 4 tiles (Ahi, Alo, Bhi, Blo), each 128 rows x 40 bf16 pitch.
#define PITCH_E   40                         // bf16 elements per row (80 bytes)
#define TILE_E    (128 * PITCH_E)            // 5120 elems / 10240 B
#define STAGE_E   (4 * TILE_E)               // 20480 elems / 40960 B
#define GSMEM_BYTES (2 * STAGE_E * 2)        // 81920 B

__device__ __forceinline__ uint32_t smem_u32(const void* p) {
    uint32_t a;
    asm("{ .reg .u64 t; cvta.to.shared.u64 t, %1; cvt.u32.u64 %0, t; }" : "=r"(a) : "l"(p));
    return a;
}
__device__ __forceinline__ void cp16(uint32_t dst, const void* src) {
    asm volatile("cp.async.cg.shared.global [%0], [%1], 16;" :: "r"(dst), "l"(src));
}
__device__ __forceinline__ void mma_bf16(float* c, const uint32_t* a, const uint32_t* b) {
    asm volatile(
        "mma.sync.aligned.m16n8k16.row.col.f32.bf16.bf16.f32 "
        "{%0,%1,%2,%3}, {%4,%5,%6,%7}, {%8,%9}, {%0,%1,%2,%3};"
        : "+f"(c[0]), "+f"(c[1]), "+f"(c[2]), "+f"(c[3])
        : "r"(a[0]), "r"(a[1]), "r"(a[2]), "r"(a[3]), "r"(b[0]), "r"(b[1]));
}

__global__ __launch_bounds__(256) void hmma_gemm_kernel(
    const __nv_bfloat16* __restrict__ Xhi, const __nv_bfloat16* __restrict__ Xlo,
    const __nv_bfloat16* __restrict__ Whi, const __nv_bfloat16* __restrict__ Wlo,
    const float* __restrict__ bias, float* __restrict__ Y,
    int M, int N, int K)
{
    extern __shared__ __nv_bfloat16 sm[];
    const uint32_t sb = smem_u32(sm);
    const int tid  = threadIdx.x;
    const int wid  = tid >> 5, lane = tid & 31;
    const int wm   = wid >> 2;            // 0..1 : 64-row slab
    const int wn   = wid & 3;             // 0..3 : 32-col slab
    const int gid  = lane >> 2;           // 0..7
    const int tig  = lane & 3;            // 0..3
    const int m0   = blockIdx.y * 128;
    const int n0   = blockIdx.x * 128;

    const __nv_bfloat16* srcs[4] = {
        Xhi + (size_t)m0 * K, Xlo + (size_t)m0 * K,
        Whi + (size_t)n0 * K, Wlo + (size_t)n0 * K };

    float acc[4][4][4];
    #pragma unroll
    for (int i = 0; i < 4; i++)
        #pragma unroll
        for (int j = 0; j < 4; j++)
            #pragma unroll
            for (int v = 0; v < 4; v++) acc[i][j][v] = 0.f;

    const int nk = K / 32;

    // issue async loads of k-chunk c into stage s
    auto load_chunk = [&](int c, int s) {
        const uint32_t sbase = sb + s * (STAGE_E * 2);
        #pragma unroll
        for (int t = 0; t < 4; t++) {
            #pragma unroll
            for (int j = 0; j < 2; j++) {
                const int i   = tid + 256 * j;        // 0..511
                const int row = i >> 2;
                const int kc  = i & 3;
                cp16(sbase + t * (TILE_E * 2) + row * (PITCH_E * 2) + kc * 16,
                     srcs[t] + (size_t)row * K + c * 32 + kc * 8);
            }
        }
    };

    load_chunk(0, 0);
    asm volatile("cp.async.commit_group;");

    for (int c = 0; c < nk; c++) {
        if (c + 1 < nk) {
            load_chunk(c + 1, (c + 1) & 1);
            asm volatile("cp.async.commit_group;");
            asm volatile("cp.async.wait_group 1;");
        } else {
            asm volatile("cp.async.wait_group 0;");
        }
        __syncthreads();

        const __nv_bfloat16* Ah = sm + (c & 1) * STAGE_E;
        const __nv_bfloat16* Al = Ah + TILE_E;
        const __nv_bfloat16* Bh = Ah + 2 * TILE_E;
        const __nv_bfloat16* Bl = Ah + 3 * TILE_E;

        #pragma unroll
        for (int ks = 0; ks < 2; ks++) {
            const int k16 = ks * 16;
            uint32_t ah[4][4], al[4][4], bh[4][2], bl[4][2];
            #pragma unroll
            for (int mf = 0; mf < 4; mf++) {
                const int row = wm * 64 + mf * 16 + gid;
                const __nv_bfloat16* p = Ah + row * PITCH_E + k16 + tig * 2;
                ah[mf][0] = *(const uint32_t*)(p);
                ah[mf][1] = *(const uint32_t*)(p + 8 * PITCH_E);
                ah[mf][2] = *(const uint32_t*)(p + 8);
                ah[mf][3] = *(const uint32_t*)(p + 8 * PITCH_E + 8);
                const __nv_bfloat16* q = Al + row * PITCH_E + k16 + tig * 2;
                al[mf][0] = *(const uint32_t*)(q);
                al[mf][1] = *(const uint32_t*)(q + 8 * PITCH_E);
                al[mf][2] = *(const uint32_t*)(q + 8);
                al[mf][3] = *(const uint32_t*)(q + 8 * PITCH_E + 8);
            }
            #pragma unroll
            for (int nf = 0; nf < 4; nf++) {
                const int rown = wn * 32 + nf * 8 + gid;
                const __nv_bfloat16* p = Bh + rown * PITCH_E + k16 + tig * 2;
                bh[nf][0] = *(const uint32_t*)(p);
                bh[nf][1] = *(const uint32_t*)(p + 8);
                const __nv_bfloat16* q = Bl + rown * PITCH_E + k16 + tig * 2;
                bl[nf][0] = *(const uint32_t*)(q);
                bl[nf][1] = *(const uint32_t*)(q + 8);
            }
            #pragma unroll
            for (int mf = 0; mf < 4; mf++)
                #pragma unroll
                for (int nf = 0; nf < 4; nf++) {
                    mma_bf16(acc[mf][nf], ah[mf], bh[nf]);
                    mma_bf16(acc[mf][nf], ah[mf], bl[nf]);
                    mma_bf16(acc[mf][nf], al[mf], bh[nf]);
                }
        }
        __syncthreads();
    }

    // epilogue: c0 = C[gid][2tig], c1 = +1, c2 = C[gid+8][2tig], c3 = +1
    #pragma unroll
    for (int mf = 0; mf < 4; mf++) {
        const int row = m0 + wm * 64 + mf * 16 + gid;
        #pragma unroll
        for (int nf = 0; nf < 4; nf++) {
            const int col = n0 + wn * 32 + nf * 8 + 2 * tig;
            const float b0 = bias ? bias[col] : 0.f;
            const float b1 = bias ? bias[col + 1] : 0.f;
            float2 v0 = make_float2(acc[mf][nf][0] + b0, acc[mf][nf][1] + b1);
            float2 v1 = make_float2(acc[mf][nf][2] + b0, acc[mf][nf][3] + b1);
            *(float2*)&Y[(size_t)row * N + col]       = v0;
            *(float2*)&Y[(size_t)(row + 8) * N + col] = v1;
        }
    }
}

// ---------------- causal GQA flash attention (fp32) ----------------
#define QS_PITCH 132
#define KT_PITCH 68
#define ES_PITCH 68

__global__ __launch_bounds__(256) void attn_kernel(
    const float* __restrict__ gq, const float* __restrict__ gk,
    const float* __restrict__ gv, float* __restrict__ gout)
{
    extern __shared__ float smf[];
    float* Qs  = smf;
    float* Kst = Qs + 64 * QS_PITCH;
    float* Vs  = Kst + 128 * KT_PITCH;
    float* Es  = Vs + 64 * QS_PITCH;
    float* den = Es + 64 * ES_PITCH;

    const int bh  = blockIdx.y;
    const int b   = bh / NQ_;
    const int h   = bh % NQ_;
    const int kvh = h / GQ_;
    const int q0  = blockIdx.x * 64;

    const int tid = threadIdx.x;
    const int tx  = tid & 15;
    const int ty  = tid >> 4;

    for (int i = tid; i < 64 * 32; i += 256) {
        const int row = i >> 5;
        const int c   = (i & 31) * 4;
        float4 v = *(const float4*)&gq[((((size_t)b * T_ + q0 + row) * NQ_) + h) * HD_ + c];
        *(float4*)&Qs[row * QS_PITCH + c] = v;
    }
    if (tid < 64) den[tid] = 0.f;

    float acc[4][8];
    #pragma unroll
    for (int r = 0; r < 4; r++)
        #pragma unroll
        for (int j = 0; j < 8; j++) acc[r][j] = 0.f;

    const int nkb = blockIdx.x + 1;
    for (int kb = 0; kb < nkb; kb++) {
        __syncthreads();
        for (int i = tid; i < 64 * 32; i += 256) {
            const int row = i >> 5;
            const int c   = (i & 31) * 4;
            const size_t base = ((((size_t)b * T_ + kb * 64 + row) * NKV_) + kvh) * HD_ + c;
            float4 kvec = *(const float4*)&gk[base];
            Kst[(c + 0) * KT_PITCH + row] = kvec.x;
            Kst[(c + 1) * KT_PITCH + row] = kvec.y;
            Kst[(c + 2) * KT_PITCH + row] = kvec.z;
            Kst[(c + 3) * KT_PITCH + row] = kvec.w;
            *(float4*)&Vs[row * QS_PITCH + c] = *(const float4*)&gv[base];
        }
        __syncthreads();

        float s[4][4];
        #pragma unroll
        for (int r = 0; r < 4; r++)
            #pragma unroll
            for (int c = 0; c < 4; c++) s[r][c] = 0.f;

        #pragma unroll 4
        for (int d = 0; d < HD_; d++) {
            float qv[4];
            #pragma unroll
            for (int r = 0; r < 4; r++) qv[r] = Qs[(ty * 4 + r) * QS_PITCH + d];
            float4 kv = *(float4*)&Kst[d * KT_PITCH + tx * 4];
            const float kvv[4] = {kv.x, kv.y, kv.z, kv.w};
            #pragma unroll
            for (int r = 0; r < 4; r++)
                #pragma unroll
                for (int c = 0; c < 4; c++)
                    s[r][c] = fmaf(qv[r], kvv[c], s[r][c]);
        }

        #pragma unroll
        for (int r = 0; r < 4; r++) {
            const int qpos = q0 + ty * 4 + r;
            float4 ev;
            float e[4];
            #pragma unroll
            for (int c = 0; c < 4; c++) {
                const int kpos = kb * 64 + tx * 4 + c;
                float val = s[r][c] * MULT_;
                val = MAX_ATTN_ * tanhf(val * (1.0f / MAX_ATTN_));
                e[c] = (kpos <= qpos) ? expf(val) : 0.f;
            }
            ev.x = e[0]; ev.y = e[1]; ev.z = e[2]; ev.w = e[3];
            *(float4*)&Es[(ty * 4 + r) * ES_PITCH + tx * 4] = ev;
        }
        __syncthreads();

        if (tid < 64) {
            float sum = 0.f;
            #pragma unroll 8
            for (int j = 0; j < 64; j++) sum += Es[tid * ES_PITCH + j];
            den[tid] += sum;
        }

        #pragma unroll 4
        for (int k = 0; k < 64; k++) {
            float e[4];
            #pragma unroll
            for (int r = 0; r < 4; r++) e[r] = Es[(ty * 4 + r) * ES_PITCH + k];
            float4 va = *(float4*)&Vs[k * QS_PITCH + tx * 8];
            float4 vb = *(float4*)&Vs[k * QS_PITCH + tx * 8 + 4];
            const float vv[8] = {va.x, va.y, va.z, va.w, vb.x, vb.y, vb.z, vb.w};
            #pragma unroll
            for (int r = 0; r < 4; r++)
                #pragma unroll
                for (int j = 0; j < 8; j++)
                    acc[r][j] = fmaf(e[r], vv[j], acc[r][j]);
        }
    }
    __syncthreads();

    #pragma unroll
    for (int r = 0; r < 4; r++) {
        const int row = q0 + ty * 4 + r;
        const float inv = 1.f / den[ty * 4 + r];
        float4 oa, ob;
        oa.x = acc[r][0] * inv; oa.y = acc[r][1] * inv;
        oa.z = acc[r][2] * inv; oa.w = acc[r][3] * inv;
        ob.x = acc[r][4] * inv; ob.y = acc[r][5] * inv;
        ob.z = acc[r][6] * inv; ob.w = acc[r][7] * inv;
        float* dst = &gout[((((size_t)b * T_ + row) * NQ_) + h) * HD_ + tx * 8];
        *(float4*)&dst[0] = oa;
        *(float4*)&dst[4] = ob;
    }
}

// ---------------- launch ----------------
extern "C" void kernel_launch(void* const* d_in, const int* in_sizes, int n_in,
                              void* d_out, int out_size)
{
    const float* query = (const float*)d_in[0];
    const float* key   = (const float*)d_in[1];
    const float* value = (const float*)d_in[2];
    const float* wq = (const float*)d_in[4];
    const float* bq = (const float*)d_in[5];
    const float* wk = (const float*)d_in[6];
    const float* bk = (const float*)d_in[7];
    const float* wv = (const float*)d_in[8];
    const float* bv = (const float*)d_in[9];
    const float* wo = (const float*)d_in[10];
    float* out = (float*)d_out;

    float *qp, *kp, *vp, *ap;
    cudaGetSymbolAddress((void**)&qp, g_q);
    cudaGetSymbolAddress((void**)&kp, g_k);
    cudaGetSymbolAddress((void**)&vp, g_v);
    cudaGetSymbolAddress((void**)&ap, g_attn);
    __nv_bfloat16 *xqh, *xql, *xkh, *xkl, *xvh, *xvl, *wth, *wtl;
    cudaGetSymbolAddress((void**)&xqh, g_xq_hi);
    cudaGetSymbolAddress((void**)&xql, g_xq_lo);
    cudaGetSymbolAddress((void**)&xkh, g_xk_hi);
    cudaGetSymbolAddress((void**)&xkl, g_xk_lo);
    cudaGetSymbolAddress((void**)&xvh, g_xv_hi);
    cudaGetSymbolAddress((void**)&xvl, g_xv_lo);
    cudaGetSymbolAddress((void**)&wth, g_wt_hi);
    cudaGetSymbolAddress((void**)&wtl, g_wt_lo);

    cudaFuncSetAttribute(hmma_gemm_kernel, cudaFuncAttributeMaxDynamicSharedMemorySize, GSMEM_BYTES);

    const int M = M_ROWS;
    const int n4 = M * D_ / 4;
    const dim3 tb(32, 8);

    // 0: rope table
    rope_table_kernel<<<(T_ * 64) / 256, 256>>>();
    // 1-3: input splits
    conv_split_kernel<<<(n4 + 255) / 256, 256>>>(query, xqh, xql, n4);
    conv_split_kernel<<<(n4 + 255) / 256, 256>>>(key,   xkh, xkl, n4);
    conv_split_kernel<<<(n4 + 255) / 256, 256>>>(value, xvh, xvl, n4);
    // 4: transpose wq ; 5: Q GEMM (ncu target)
    transpose_split_kernel<<<dim3((NQ_ * HD_) / 32, D_ / 32), tb>>>(wq, wth, wtl, D_, NQ_ * HD_);
    hmma_gemm_kernel<<<dim3((NQ_ * HD_) / 128, M / 128), 256, GSMEM_BYTES>>>(
        xqh, xql, wth, wtl, bq, qp, M, NQ_ * HD_, D_);
    // 6-7: K
    transpose_split_kernel<<<dim3((NKV_ * HD_) / 32, D_ / 32), tb>>>(wk, wth, wtl, D_, NKV_ * HD_);
    hmma_gemm_kernel<<<dim3((NKV_ * HD_) / 128, M / 128), 256, GSMEM_BYTES>>>(
        xkh, xkl, wth, wtl, bk, kp, M, NKV_ * HD_, D_);
    // 8-9: V
    transpose_split_kernel<<<dim3((NKV_ * HD_) / 32, D_ / 32), tb>>>(wv, wth, wtl, D_, NKV_ * HD_);
    hmma_gemm_kernel<<<dim3((NKV_ * HD_) / 128, M / 128), 256, GSMEM_BYTES>>>(
        xvh, xvl, wth, wtl, bv, vp, M, NKV_ * HD_, D_);
    // 10-11: rope
    const int nq_pairs = B_ * T_ * NQ_ * 64;
    const int nk_pairs = B_ * T_ * NKV_ * 64;
    rope_apply_kernel<<<(nq_pairs + 255) / 256, 256>>>(qp, NQ_, nq_pairs);
    rope_apply_kernel<<<(nk_pairs + 255) / 256, 256>>>(kp, NKV_, nk_pairs);
    // 12: attention
    const size_t asmem = (size_t)(64 * QS_PITCH + 128 * KT_PITCH + 64 * QS_PITCH
                                  + 64 * ES_PITCH + 64) * sizeof(float);
    cudaFuncSetAttribute(attn_kernel, cudaFuncAttributeMaxDynamicSharedMemorySize, (int)asmem);
    attn_kernel<<<dim3(T_ / 64, B_ * NQ_), 256, asmem>>>(qp, kp, vp, ap);
    // 13: split attn output (reuse xq planes)
    conv_split_kernel<<<(n4 + 255) / 256, 256>>>(ap, xqh, xql, n4);
    // 14-15: O GEMM
    transpose_split_kernel<<<dim3(D_ / 32, (NQ_ * HD_) / 32), tb>>>(wo, wth, wtl, NQ_ * HD_, D_);
    hmma_gemm_kernel<<<dim3(D_ / 128, M / 128), 256, GSMEM_BYTES>>>(
        xqh, xql, wth, wtl, nullptr, out, M, D_, NQ_ * HD_);
}

// round 5
// speedup vs baseline: 2.4355x; 1.1897x over previous
#include <cuda_runtime.h>
#include <cuda_bf16.h>
#include <cstdint>
#include <math.h>

#define B_   2
#define T_   1024
#define D_   6144
#define NQ_  48
#define NKV_ 8
#define HD_  128
#define GQ_  (NQ_ / NKV_)
#define MULT_     0.08838834764831845f
#define MAX_ATTN_ 30.0f
#define M_ROWS (B_ * T_)           // 2048

// ---------------- scratch (__device__ globals; no allocation) ----------------
__device__ float g_q[(size_t)B_ * T_ * NQ_ * HD_];
__device__ float g_k[(size_t)B_ * T_ * NKV_ * HD_];
__device__ float g_v[(size_t)B_ * T_ * NKV_ * HD_];
__device__ float2 g_rope[T_ * 64];

// bf16 split planes
__device__ __nv_bfloat16 g_xq_hi[(size_t)M_ROWS * D_];
__device__ __nv_bfloat16 g_xq_lo[(size_t)M_ROWS * D_];
__device__ __nv_bfloat16 g_xk_hi[(size_t)M_ROWS * D_];
__device__ __nv_bfloat16 g_xk_lo[(size_t)M_ROWS * D_];
__device__ __nv_bfloat16 g_xv_hi[(size_t)M_ROWS * D_];
__device__ __nv_bfloat16 g_xv_lo[(size_t)M_ROWS * D_];
__device__ __nv_bfloat16 g_wt_hi[(size_t)D_ * D_];   // [N,K] transposed weight, reused
__device__ __nv_bfloat16 g_wt_lo[(size_t)D_ * D_];

// ---------------- rope table + apply ----------------
__global__ void rope_table_kernel() {
    const int i = blockIdx.x * blockDim.x + threadIdx.x;   // < T_*64
    const int t = i >> 6, j = i & 63;
    const double invf = exp(-log(10000.0) * (double)j / 64.0);
    double ph = (double)t * invf;
    const double twopi = 6.283185307179586476925286766559;
    ph -= twopi * floor(ph / twopi);
    float s, c;
    sincosf((float)ph, &s, &c);
    g_rope[i] = make_float2(c, s);
}
__global__ __launch_bounds__(256) void rope_apply_kernel(float* __restrict__ x, int H, int total) {
    const int idx = blockIdx.x * blockDim.x + threadIdx.x;
    if (idx >= total) return;
    const int j = idx & 63;
    const int lin = idx >> 6;
    const int t = (lin / H) % T_;
    const float2 cs = g_rope[t * 64 + j];
    const size_t base = (size_t)lin * HD_;
    const float x1 = x[base + j];
    const float x2 = x[base + j + 64];
    x[base + j]      = x1 * cs.x - x2 * cs.y;
    x[base + j + 64] = x2 * cs.x + x1 * cs.y;
}

// ---------------- fp32 -> (hi, lo) bf16 split ----------------
__global__ __launch_bounds__(256) void conv_split_kernel(
    const float* __restrict__ x, __nv_bfloat16* __restrict__ hi,
    __nv_bfloat16* __restrict__ lo, int n4)
{
    const int i = blockIdx.x * blockDim.x + threadIdx.x;
    if (i >= n4) return;
    const float4 v = ((const float4*)x)[i];
    __nv_bfloat16 h0 = __float2bfloat16_rn(v.x);
    __nv_bfloat16 h1 = __float2bfloat16_rn(v.y);
    __nv_bfloat16 h2 = __float2bfloat16_rn(v.z);
    __nv_bfloat16 h3 = __float2bfloat16_rn(v.w);
    __nv_bfloat162* H = (__nv_bfloat162*)hi;
    __nv_bfloat162* L = (__nv_bfloat162*)lo;
    H[2 * i]     = __nv_bfloat162(h0, h1);
    H[2 * i + 1] = __nv_bfloat162(h2, h3);
    L[2 * i]     = __nv_bfloat162(__float2bfloat16_rn(v.x - __bfloat162float(h0)),
                                  __float2bfloat16_rn(v.y - __bfloat162float(h1)));
    L[2 * i + 1] = __nv_bfloat162(__float2bfloat16_rn(v.z - __bfloat162float(h2)),
                                  __float2bfloat16_rn(v.w - __bfloat162float(h3)));
}

// ---------------- W[K,N] fp32 -> Wt[N,K] (hi, lo) bf16 ----------------
__global__ void transpose_split_kernel(
    const float* __restrict__ W, __nv_bfloat16* __restrict__ Thi,
    __nv_bfloat16* __restrict__ Tlo, int K, int N)
{
    __shared__ float s[32][33];
    const int k0 = blockIdx.y * 32, n0 = blockIdx.x * 32;
    const int tx = threadIdx.x, ty = threadIdx.y;  // 32 x 8
    #pragma unroll
    for (int i = 0; i < 4; i++)
        s[ty + 8 * i][tx] = W[(size_t)(k0 + ty + 8 * i) * N + n0 + tx];
    __syncthreads();
    #pragma unroll
    for (int i = 0; i < 4; i++) {
        const float v = s[tx][ty + 8 * i];
        const __nv_bfloat16 h = __float2bfloat16_rn(v);
        const size_t o = (size_t)(n0 + ty + 8 * i) * K + k0 + tx;
        Thi[o] = h;
        Tlo[o] = __float2bfloat16_rn(v - __bfloat162float(h));
    }
}

// ---------------- common MMA helper ----------------
__device__ __forceinline__ uint32_t smem_u32(const void* p) {
    uint32_t a;
    asm("{ .reg .u64 t; cvta.to.shared.u64 t, %1; cvt.u32.u64 %0, t; }" : "=r"(a) : "l"(p));
    return a;
}
__device__ __forceinline__ void cp16(uint32_t dst, const void* src) {
    asm volatile("cp.async.cg.shared.global [%0], [%1], 16;" :: "r"(dst), "l"(src));
}
__device__ __forceinline__ void mma_bf16(float* c, const uint32_t* a, const uint32_t* b) {
    asm volatile(
        "mma.sync.aligned.m16n8k16.row.col.f32.bf16.bf16.f32 "
        "{%0,%1,%2,%3}, {%4,%5,%6,%7}, {%8,%9}, {%0,%1,%2,%3};"
        : "+f"(c[0]), "+f"(c[1]), "+f"(c[2]), "+f"(c[3])
        : "r"(a[0]), "r"(a[1]), "r"(a[2]), "r"(a[3]), "r"(b[0]), "r"(b[1]));
}

// ---------------- split-bf16 HMMA GEMM: Y[M,N] = X[M,K] @ Wt[N,K]^T ---------
#define PITCH_E   40
#define TILE_E    (128 * PITCH_E)
#define STAGE_E   (4 * TILE_E)
#define GSMEM_BYTES (2 * STAGE_E * 2)        // 81920 B

__global__ __launch_bounds__(256) void hmma_gemm_kernel(
    const __nv_bfloat16* __restrict__ Xhi, const __nv_bfloat16* __restrict__ Xlo,
    const __nv_bfloat16* __restrict__ Whi, const __nv_bfloat16* __restrict__ Wlo,
    const float* __restrict__ bias, float* __restrict__ Y,
    int M, int N, int K)
{
    extern __shared__ __nv_bfloat16 sm[];
    const uint32_t sb = smem_u32(sm);
    const int tid  = threadIdx.x;
    const int wid  = tid >> 5, lane = tid & 31;
    const int wm   = wid >> 2;
    const int wn   = wid & 3;
    const int gid  = lane >> 2;
    const int tig  = lane & 3;
    const int m0   = blockIdx.y * 128;
    const int n0   = blockIdx.x * 128;

    const __nv_bfloat16* srcs[4] = {
        Xhi + (size_t)m0 * K, Xlo + (size_t)m0 * K,
        Whi + (size_t)n0 * K, Wlo + (size_t)n0 * K };

    float acc[4][4][4];
    #pragma unroll
    for (int i = 0; i < 4; i++)
        #pragma unroll
        for (int j = 0; j < 4; j++)
            #pragma unroll
            for (int v = 0; v < 4; v++) acc[i][j][v] = 0.f;

    const int nk = K / 32;

    auto load_chunk = [&](int c, int s) {
        const uint32_t sbase = sb + s * (STAGE_E * 2);
        #pragma unroll
        for (int t = 0; t < 4; t++) {
            #pragma unroll
            for (int j = 0; j < 2; j++) {
                const int i   = tid + 256 * j;
                const int row = i >> 2;
                const int kc  = i & 3;
                cp16(sbase + t * (TILE_E * 2) + row * (PITCH_E * 2) + kc * 16,
                     srcs[t] + (size_t)row * K + c * 32 + kc * 8);
            }
        }
    };

    load_chunk(0, 0);
    asm volatile("cp.async.commit_group;");

    for (int c = 0; c < nk; c++) {
        if (c + 1 < nk) {
            load_chunk(c + 1, (c + 1) & 1);
            asm volatile("cp.async.commit_group;");
            asm volatile("cp.async.wait_group 1;");
        } else {
            asm volatile("cp.async.wait_group 0;");
        }
        __syncthreads();

        const __nv_bfloat16* Ah = sm + (c & 1) * STAGE_E;
        const __nv_bfloat16* Al = Ah + TILE_E;
        const __nv_bfloat16* Bh = Ah + 2 * TILE_E;
        const __nv_bfloat16* Bl = Ah + 3 * TILE_E;

        #pragma unroll
        for (int ks = 0; ks < 2; ks++) {
            const int k16 = ks * 16;
            uint32_t ah[4][4], al[4][4], bh[4][2], bl[4][2];
            #pragma unroll
            for (int mf = 0; mf < 4; mf++) {
                const int row = wm * 64 + mf * 16 + gid;
                const __nv_bfloat16* p = Ah + row * PITCH_E + k16 + tig * 2;
                ah[mf][0] = *(const uint32_t*)(p);
                ah[mf][1] = *(const uint32_t*)(p + 8 * PITCH_E);
                ah[mf][2] = *(const uint32_t*)(p + 8);
                ah[mf][3] = *(const uint32_t*)(p + 8 * PITCH_E + 8);
                const __nv_bfloat16* q = Al + row * PITCH_E + k16 + tig * 2;
                al[mf][0] = *(const uint32_t*)(q);
                al[mf][1] = *(const uint32_t*)(q + 8 * PITCH_E);
                al[mf][2] = *(const uint32_t*)(q + 8);
                al[mf][3] = *(const uint32_t*)(q + 8 * PITCH_E + 8);
            }
            #pragma unroll
            for (int nf = 0; nf < 4; nf++) {
                const int rown = wn * 32 + nf * 8 + gid;
                const __nv_bfloat16* p = Bh + rown * PITCH_E + k16 + tig * 2;
                bh[nf][0] = *(const uint32_t*)(p);
                bh[nf][1] = *(const uint32_t*)(p + 8);
                const __nv_bfloat16* q = Bl + rown * PITCH_E + k16 + tig * 2;
                bl[nf][0] = *(const uint32_t*)(q);
                bl[nf][1] = *(const uint32_t*)(q + 8);
            }
            #pragma unroll
            for (int mf = 0; mf < 4; mf++)
                #pragma unroll
                for (int nf = 0; nf < 4; nf++) {
                    mma_bf16(acc[mf][nf], ah[mf], bh[nf]);
                    mma_bf16(acc[mf][nf], ah[mf], bl[nf]);
                    mma_bf16(acc[mf][nf], al[mf], bh[nf]);
                }
        }
        __syncthreads();
    }

    #pragma unroll
    for (int mf = 0; mf < 4; mf++) {
        const int row = m0 + wm * 64 + mf * 16 + gid;
        #pragma unroll
        for (int nf = 0; nf < 4; nf++) {
            const int col = n0 + wn * 32 + nf * 8 + 2 * tig;
            const float b0 = bias ? bias[col] : 0.f;
            const float b1 = bias ? bias[col + 1] : 0.f;
            float2 v0 = make_float2(acc[mf][nf][0] + b0, acc[mf][nf][1] + b1);
            float2 v1 = make_float2(acc[mf][nf][2] + b0, acc[mf][nf][3] + b1);
            *(float2*)&Y[(size_t)row * N + col]       = v0;
            *(float2*)&Y[(size_t)(row + 8) * N + col] = v1;
        }
    }
}

// ---------------- HMMA split-bf16 causal GQA flash attention -----------------
// BQ=128 (8 warps x 16 q-rows), BK=64, HD=128.
#define AQ_P 136     // bf16 pitch for Q,K tiles
#define AV_P 72      // bf16 pitch for Vt
#define AS_P 132     // fp32 pitch for V staging
#define ASMEM_BYTES ((2 * 128 * AQ_P + 2 * 64 * AQ_P + 2 * 128 * AV_P) * 2 + 64 * AS_P * 4)

__device__ __forceinline__ float softcap_exp(float s) {
    // exp(30 * tanh(s*MULT/30)) via tanh(x) = 1 - 2/(e^{2x}+1)
    const float x = s * (MULT_ / MAX_ATTN_);
    const float e2 = __expf(2.f * x);
    const float cap = MAX_ATTN_ - __fdividef(2.f * MAX_ATTN_, e2 + 1.f);
    return __expf(cap);
}

__global__ __launch_bounds__(256) void attn_hmma_kernel(
    const float* __restrict__ gq, const float* __restrict__ gk,
    const float* __restrict__ gv, __nv_bfloat16* __restrict__ outh,
    __nv_bfloat16* __restrict__ outl)
{
    extern __shared__ __nv_bfloat16 as2[];
    __nv_bfloat16* Qh  = as2;
    __nv_bfloat16* Ql  = Qh + 128 * AQ_P;
    __nv_bfloat16* Kh  = Ql + 128 * AQ_P;
    __nv_bfloat16* Kl  = Kh + 64 * AQ_P;
    __nv_bfloat16* Vth = Kl + 64 * AQ_P;
    __nv_bfloat16* Vtl = Vth + 128 * AV_P;
    float*         Vst = (float*)(Vtl + 128 * AV_P);

    const int bh  = blockIdx.y;
    const int b   = bh / NQ_;
    const int h   = bh % NQ_;
    const int kvh = h / GQ_;
    const int q0  = blockIdx.x * 128;

    const int tid = threadIdx.x;
    const int wid = tid >> 5, lane = tid & 31;
    const int gid = lane >> 2, tig = lane & 3;

    // ---- load + split Q tile (128 x 128) ----
    for (int i = tid; i < 128 * 32; i += 256) {
        const int row = i >> 5, c = (i & 31) * 4;
        const float4 v = *(const float4*)&gq[((((size_t)b * T_ + q0 + row) * NQ_) + h) * HD_ + c];
        __nv_bfloat16 h0 = __float2bfloat16_rn(v.x), h1 = __float2bfloat16_rn(v.y);
        __nv_bfloat16 h2 = __float2bfloat16_rn(v.z), h3 = __float2bfloat16_rn(v.w);
        *(__nv_bfloat162*)&Qh[row * AQ_P + c]     = __nv_bfloat162(h0, h1);
        *(__nv_bfloat162*)&Qh[row * AQ_P + c + 2] = __nv_bfloat162(h2, h3);
        *(__nv_bfloat162*)&Ql[row * AQ_P + c] =
            __nv_bfloat162(__float2bfloat16_rn(v.x - __bfloat162float(h0)),
                           __float2bfloat16_rn(v.y - __bfloat162float(h1)));
        *(__nv_bfloat162*)&Ql[row * AQ_P + c + 2] =
            __nv_bfloat162(__float2bfloat16_rn(v.z - __bfloat162float(h2)),
                           __float2bfloat16_rn(v.w - __bfloat162float(h3)));
    }

    float oacc[16][4];
    #pragma unroll
    for (int n = 0; n < 16; n++)
        #pragma unroll
        for (int v = 0; v < 4; v++) oacc[n][v] = 0.f;
    float rs0 = 0.f, rs1 = 0.f;

    const int qg0 = q0 + wid * 16 + gid;
    const int qg1 = qg0 + 8;

    const int nkb = 2 * blockIdx.x + 2;
    for (int kb = 0; kb < nkb; kb++) {
        __syncthreads();
        // ---- load K (split) + stage V ----
        for (int i = tid; i < 64 * 32; i += 256) {
            const int row = i >> 5, c = (i & 31) * 4;
            const size_t base = ((((size_t)b * T_ + kb * 64 + row) * NKV_) + kvh) * HD_ + c;
            const float4 kv = *(const float4*)&gk[base];
            __nv_bfloat16 h0 = __float2bfloat16_rn(kv.x), h1 = __float2bfloat16_rn(kv.y);
            __nv_bfloat16 h2 = __float2bfloat16_rn(kv.z), h3 = __float2bfloat16_rn(kv.w);
            *(__nv_bfloat162*)&Kh[row * AQ_P + c]     = __nv_bfloat162(h0, h1);
            *(__nv_bfloat162*)&Kh[row * AQ_P + c + 2] = __nv_bfloat162(h2, h3);
            *(__nv_bfloat162*)&Kl[row * AQ_P + c] =
                __nv_bfloat162(__float2bfloat16_rn(kv.x - __bfloat162float(h0)),
                               __float2bfloat16_rn(kv.y - __bfloat162float(h1)));
            *(__nv_bfloat162*)&Kl[row * AQ_P + c + 2] =
                __nv_bfloat162(__float2bfloat16_rn(kv.z - __bfloat162float(h2)),
                               __float2bfloat16_rn(kv.w - __bfloat162float(h3)));
            *(float4*)&Vst[row * AS_P + c] = *(const float4*)&gv[base];
        }
        __syncthreads();
        // ---- transpose V stage -> Vt hi/lo ----
        {
            const int d = tid & 127;
            const int th = (tid >> 7) * 32;
            #pragma unroll
            for (int t2 = 0; t2 < 32; t2 += 2) {
                const int t = th + t2;
                const float v0 = Vst[t * AS_P + d];
                const float v1 = Vst[(t + 1) * AS_P + d];
                __nv_bfloat16 h0 = __float2bfloat16_rn(v0), h1 = __float2bfloat16_rn(v1);
                *(__nv_bfloat162*)&Vth[d * AV_P + t] = __nv_bfloat162(h0, h1);
                *(__nv_bfloat162*)&Vtl[d * AV_P + t] =
                    __nv_bfloat162(__float2bfloat16_rn(v0 - __bfloat162float(h0)),
                                   __float2bfloat16_rn(v1 - __bfloat162float(h1)));
            }
        }
        __syncthreads();

        // ---- S = Q K^T (16 x 64 per warp), 3-term split ----
        float sacc[8][4];
        #pragma unroll
        for (int nf = 0; nf < 8; nf++)
            #pragma unroll
            for (int v = 0; v < 4; v++) sacc[nf][v] = 0.f;

        #pragma unroll
        for (int ks = 0; ks < 8; ks++) {
            const int ko = ks * 16 + tig * 2;
            const __nv_bfloat16* pa = Qh + (wid * 16 + gid) * AQ_P + ko;
            uint32_t ah[4] = { *(const uint32_t*)pa, *(const uint32_t*)(pa + 8 * AQ_P),
                               *(const uint32_t*)(pa + 8), *(const uint32_t*)(pa + 8 * AQ_P + 8) };
            const __nv_bfloat16* pal = Ql + (wid * 16 + gid) * AQ_P + ko;
            uint32_t al[4] = { *(const uint32_t*)pal, *(const uint32_t*)(pal + 8 * AQ_P),
                               *(const uint32_t*)(pal + 8), *(const uint32_t*)(pal + 8 * AQ_P + 8) };
            #pragma unroll
            for (int nf = 0; nf < 8; nf++) {
                const __nv_bfloat16* pb = Kh + (nf * 8 + gid) * AQ_P + ko;
                uint32_t bfh[2] = { *(const uint32_t*)pb, *(const uint32_t*)(pb + 8) };
                const __nv_bfloat16* pbl = Kl + (nf * 8 + gid) * AQ_P + ko;
                uint32_t bfl[2] = { *(const uint32_t*)pbl, *(const uint32_t*)(pbl + 8) };
                mma_bf16(sacc[nf], ah, bfh);
                mma_bf16(sacc[nf], ah, bfl);
                mma_bf16(sacc[nf], al, bfh);
            }
        }

        // ---- soft-cap + causal mask + exp; split P into hi/lo fragments ----
        uint32_t ph[8][2], pl[8][2];
        #pragma unroll
        for (int nf = 0; nf < 8; nf++) {
            const int kg = kb * 64 + nf * 8 + tig * 2;
            float p0 = (kg     <= qg0) ? softcap_exp(sacc[nf][0]) : 0.f;
            float p1 = (kg + 1 <= qg0) ? softcap_exp(sacc[nf][1]) : 0.f;
            float p2 = (kg     <= qg1) ? softcap_exp(sacc[nf][2]) : 0.f;
            float p3 = (kg + 1 <= qg1) ? softcap_exp(sacc[nf][3]) : 0.f;
            rs0 += p0 + p1;
            rs1 += p2 + p3;
            __nv_bfloat16 b0 = __float2bfloat16_rn(p0), b1 = __float2bfloat16_rn(p1);
            __nv_bfloat16 b2 = __float2bfloat16_rn(p2), b3 = __float2bfloat16_rn(p3);
            __nv_bfloat162 t0(b0, b1), t1(b2, b3);
            ph[nf][0] = *(uint32_t*)&t0;
            ph[nf][1] = *(uint32_t*)&t1;
            __nv_bfloat162 u0(__float2bfloat16_rn(p0 - __bfloat162float(b0)),
                              __float2bfloat16_rn(p1 - __bfloat162float(b1)));
            __nv_bfloat162 u1(__float2bfloat16_rn(p2 - __bfloat162float(b2)),
                              __float2bfloat16_rn(p3 - __bfloat162float(b3)));
            pl[nf][0] = *(uint32_t*)&u0;
            pl[nf][1] = *(uint32_t*)&u1;
        }

        // ---- O += P V (16 x 128 per warp), 3-term split ----
        #pragma unroll
        for (int s = 0; s < 4; s++) {
            uint32_t ah2[4] = { ph[2 * s][0], ph[2 * s][1], ph[2 * s + 1][0], ph[2 * s + 1][1] };
            uint32_t al2[4] = { pl[2 * s][0], pl[2 * s][1], pl[2 * s + 1][0], pl[2 * s + 1][1] };
            const int ko = s * 16 + tig * 2;
            #pragma unroll
            for (int n = 0; n < 16; n++) {
                const __nv_bfloat16* pb = Vth + (n * 8 + gid) * AV_P + ko;
                uint32_t bfh[2] = { *(const uint32_t*)pb, *(const uint32_t*)(pb + 8) };
                const __nv_bfloat16* pbl = Vtl + (n * 8 + gid) * AV_P + ko;
                uint32_t bfl[2] = { *(const uint32_t*)pbl, *(const uint32_t*)(pbl + 8) };
                mma_bf16(oacc[n], ah2, bfh);
                mma_bf16(oacc[n], ah2, bfl);
                mma_bf16(oacc[n], al2, bfh);
            }
        }
    }

    // ---- row-sum reduction within quad, normalize, split-store O ----
    rs0 += __shfl_xor_sync(0xFFFFFFFFu, rs0, 1);
    rs0 += __shfl_xor_sync(0xFFFFFFFFu, rs0, 2);
    rs1 += __shfl_xor_sync(0xFFFFFFFFu, rs1, 1);
    rs1 += __shfl_xor_sync(0xFFFFFFFFu, rs1, 2);
    const float inv0 = 1.f / rs0;
    const float inv1 = 1.f / rs1;

    const int r0 = b * T_ + q0 + wid * 16 + gid;   // FIXED: include batch offset
    #pragma unroll
    for (int n = 0; n < 16; n++) {
        const int c = h * HD_ + n * 8 + tig * 2;
        const float o0 = oacc[n][0] * inv0, o1 = oacc[n][1] * inv0;
        const float o2 = oacc[n][2] * inv1, o3 = oacc[n][3] * inv1;
        __nv_bfloat16 h0 = __float2bfloat16_rn(o0), h1 = __float2bfloat16_rn(o1);
        __nv_bfloat16 h2 = __float2bfloat16_rn(o2), h3 = __float2bfloat16_rn(o3);
        __nv_bfloat162 t0(h0, h1), t1(h2, h3);
        *(uint32_t*)&outh[(size_t)r0 * D_ + c]       = *(uint32_t*)&t0;
        *(uint32_t*)&outh[(size_t)(r0 + 8) * D_ + c] = *(uint32_t*)&t1;
        __nv_bfloat162 u0(__float2bfloat16_rn(o0 - __bfloat162float(h0)),
                          __float2bfloat16_rn(o1 - __bfloat162float(h1)));
        __nv_bfloat162 u1(__float2bfloat16_rn(o2 - __bfloat162float(h2)),
                          __float2bfloat16_rn(o3 - __bfloat162float(h3)));
        *(uint32_t*)&outl[(size_t)r0 * D_ + c]       = *(uint32_t*)&u0;
        *(uint32_t*)&outl[(size_t)(r0 + 8) * D_ + c] = *(uint32_t*)&u1;
    }
}

// ---------------- launch ----------------
extern "C" void kernel_launch(void* const* d_in, const int* in_sizes, int n_in,
                              void* d_out, int out_size)
{
    const float* query = (const float*)d_in[0];
    const float* key   = (const float*)d_in[1];
    const float* value = (const float*)d_in[2];
    const float* wq = (const float*)d_in[4];
    const float* bq = (const float*)d_in[5];
    const float* wk = (const float*)d_in[6];
    const float* bk = (const float*)d_in[7];
    const float* wv = (const float*)d_in[8];
    const float* bv = (const float*)d_in[9];
    const float* wo = (const float*)d_in[10];
    float* out = (float*)d_out;

    float *qp, *kp, *vp;
    cudaGetSymbolAddress((void**)&qp, g_q);
    cudaGetSymbolAddress((void**)&kp, g_k);
    cudaGetSymbolAddress((void**)&vp, g_v);
    __nv_bfloat16 *xqh, *xql, *xkh, *xkl, *xvh, *xvl, *wth, *wtl;
    cudaGetSymbolAddress((void**)&xqh, g_xq_hi);
    cudaGetSymbolAddress((void**)&xql, g_xq_lo);
    cudaGetSymbolAddress((void**)&xkh, g_xk_hi);
    cudaGetSymbolAddress((void**)&xkl, g_xk_lo);
    cudaGetSymbolAddress((void**)&xvh, g_xv_hi);
    cudaGetSymbolAddress((void**)&xvl, g_xv_lo);
    cudaGetSymbolAddress((void**)&wth, g_wt_hi);
    cudaGetSymbolAddress((void**)&wtl, g_wt_lo);

    cudaFuncSetAttribute(hmma_gemm_kernel, cudaFuncAttributeMaxDynamicSharedMemorySize, GSMEM_BYTES);
    cudaFuncSetAttribute(attn_hmma_kernel, cudaFuncAttributeMaxDynamicSharedMemorySize, ASMEM_BYTES);

    const int M = M_ROWS;
    const int n4 = M * D_ / 4;
    const dim3 tb(32, 8);

    rope_table_kernel<<<(T_ * 64) / 256, 256>>>();
    conv_split_kernel<<<(n4 + 255) / 256, 256>>>(query, xqh, xql, n4);
    conv_split_kernel<<<(n4 + 255) / 256, 256>>>(key,   xkh, xkl, n4);
    conv_split_kernel<<<(n4 + 255) / 256, 256>>>(value, xvh, xvl, n4);
    // Q projection
    transpose_split_kernel<<<dim3((NQ_ * HD_) / 32, D_ / 32), tb>>>(wq, wth, wtl, D_, NQ_ * HD_);
    hmma_gemm_kernel<<<dim3((NQ_ * HD_) / 128, M / 128), 256, GSMEM_BYTES>>>(
        xqh, xql, wth, wtl, bq, qp, M, NQ_ * HD_, D_);
    // K projection
    transpose_split_kernel<<<dim3((NKV_ * HD_) / 32, D_ / 32), tb>>>(wk, wth, wtl, D_, NKV_ * HD_);
    hmma_gemm_kernel<<<dim3((NKV_ * HD_) / 128, M / 128), 256, GSMEM_BYTES>>>(
        xkh, xkl, wth, wtl, bk, kp, M, NKV_ * HD_, D_);
    // V projection
    transpose_split_kernel<<<dim3((NKV_ * HD_) / 32, D_ / 32), tb>>>(wv, wth, wtl, D_, NKV_ * HD_);
    hmma_gemm_kernel<<<dim3((NKV_ * HD_) / 128, M / 128), 256, GSMEM_BYTES>>>(
        xvh, xvl, wth, wtl, bv, vp, M, NKV_ * HD_, D_);
    // rope
    const int nq_pairs = B_ * T_ * NQ_ * 64;
    const int nk_pairs = B_ * T_ * NKV_ * 64;
    rope_apply_kernel<<<(nq_pairs + 255) / 256, 256>>>(qp, NQ_, nq_pairs);
    rope_apply_kernel<<<(nk_pairs + 255) / 256, 256>>>(kp, NKV_, nk_pairs);
    // attention (writes hi/lo planes for O-GEMM directly)
    attn_hmma_kernel<<<dim3(T_ / 128, B_ * NQ_), 256, ASMEM_BYTES>>>(qp, kp, vp, xqh, xql);
    // O projection
    transpose_split_kernel<<<dim3(D_ / 32, (NQ_ * HD_) / 32), tb>>>(wo, wth, wtl, NQ_ * HD_, D_);
    hmma_gemm_kernel<<<dim3(D_ / 128, M / 128), 256, GSMEM_BYTES>>>(
        xqh, xql, wth, wtl, nullptr, out, M, D_, NQ_ * HD_);
}